// round 15
// baseline (speedup 1.0000x reference)
#include <cuda_runtime.h>
#include <cuda_fp16.h>
#include <cstdint>

// ---------------------------------------------------------------------------
// AutoconstraintModel on GB300 (harness target sm_103 — legacy mma.sync).
// R15: partner widened to 512 threads/CTA (16 warps, 4/SMSP) at occ-1 —
//      same 128-row tiles, same double-buffered cp.async, same single-chain
//      fp16 math; extra warps hide the ~1300cyc/tile barrier+epilogue+staging
//      overhead identified in the R14 profile (84us vs 63us tensor floor).
//   aux (R14-proven, ~33us): base body (R8) + label body (R12), one launch.
// rel_err 3.068e-4 (unchanged math).
// ---------------------------------------------------------------------------

#define DD 128
#define BSTR 136      // partner B smem row stride (fp16) — conflict-free
#define KSTR 264      // base B stride (fp16), K=256 — conflict-free
#define ATSTR 132     // partner A tile row stride (floats)
#define XSTR 260      // base X row stride (floats)
#define LXS 132       // label X/H row stride (floats)
#define LWS 136       // label W smem stride (fp16)

__device__ float g_base[8192 * 128];   // Base[B][128] scratch (4 MB static)

// ============================ HMMA helpers (fp16) ==========================
__device__ __forceinline__ void mma_f16(float* c, const uint32_t* a,
                                        uint32_t b0, uint32_t b1) {
    asm volatile(
        "mma.sync.aligned.m16n8k16.row.col.f32.f16.f16.f32 "
        "{%0,%1,%2,%3}, {%4,%5,%6,%7}, {%8,%9}, {%0,%1,%2,%3};"
        : "+f"(c[0]), "+f"(c[1]), "+f"(c[2]), "+f"(c[3])
        : "r"(a[0]), "r"(a[1]), "r"(a[2]), "r"(a[3]), "r"(b0), "r"(b1));
}

__device__ __forceinline__ uint32_t cvt2h(float x, float y) {
    __half2 h = __floats2half2_rn(x, y);
    return *reinterpret_cast<uint32_t*>(&h);
}
__device__ __forceinline__ void split2h(float x, float y,
                                        uint32_t& hi, uint32_t& lo) {
    __half2 h = __floats2half2_rn(x, y);
    float2 hf = __half22float2(h);
    __half2 r = __floats2half2_rn(x - hf.x, y - hf.y);
    hi = *reinterpret_cast<uint32_t*>(&h);
    lo = *reinterpret_cast<uint32_t*>(&r);
}

__device__ __forceinline__ uint32_t smem_u32(const void* p) {
    uint32_t a;
    asm("{ .reg .u64 t; cvta.to.shared.u64 t, %1; cvt.u32.u64 %0, t; }"
        : "=r"(a) : "l"(p));
    return a;
}

#define CP16(dst_u32, src_ptr) \
    asm volatile("cp.async.cg.shared.global [%0], [%1], 16;" \
                 :: "r"(dst_u32), "l"(src_ptr))
#define CP_COMMIT() asm volatile("cp.async.commit_group;" ::: "memory")
#define CP_WAIT0()  asm volatile("cp.async.wait_group 0;" ::: "memory")
#define CP_WAIT1()  asm volatile("cp.async.wait_group 1;" ::: "memory")

// ===========================================================================
// aux kernel (R14-proven): blocks [0,nBase) base body, rest label body.
// ===========================================================================
__global__ void __launch_bounds__(256, 1) aux_kernel(
    const float* __restrict__ node, const float* __restrict__ glob,
    const float* __restrict__ Wp1, const float* __restrict__ bp1,
    const float* __restrict__ Wl1, const float* __restrict__ bl1,
    const float* __restrict__ Wl2, const float* __restrict__ bl2,
    const float* __restrict__ Wl3, const float* __restrict__ bl3,
    const int* __restrict__ pgi, const int* __restrict__ pni,
    int n_per, int NL, float* __restrict__ out_label, int nBase)
{
    extern __shared__ char smc[];
    const int t = threadIdx.x;

    if ((int)blockIdx.x < nBase) {
        // ================= base body (R8, 64 graphs) =======================
        float* Xs   = (float*)smc;                   // [64][XSTR]
        __half* Bf  = (__half*)(Xs + 64 * XSTR);     // [128][KSTR]
        float* bias = (float*)(Bf + 128 * KSTR);     // [128]

        const int g0 = (int)blockIdx.x * 64;
        const uint32_t xs_u32 = smem_u32(Xs);

        #pragma unroll
        for (int i = 0; i < 8; i++) {                // cur: 2048 float4
            int f = t + i * 256;
            int g = f >> 5, c4 = (f & 31) << 2;
            const float* src = node
                + (size_t)((g0 + g + 1) * n_per - 1) * DD + c4;
            CP16(xs_u32 + (uint32_t)((g * XSTR + c4) * 4), src);
        }
        #pragma unroll
        for (int i = 0; i < 8; i++) {                // glob: 2048 float4
            int f = t + i * 256;
            int g = f >> 5, c4 = (f & 31) << 2;
            const float* src = glob + (size_t)(g0 + g) * DD + c4;
            CP16(xs_u32 + (uint32_t)((g * XSTR + 128 + c4) * 4), src);
        }
        CP_COMMIT();

        #pragma unroll
        for (int i = 0; i < 128; i++) {              // Bf[n][k] = f16(W[k][n])
            int idx = t + i * 256;
            int k = idx >> 7, n = idx & 127;
            Bf[n * KSTR + k] = __float2half_rn(
                Wp1[(size_t)(k < 128 ? k : k + 128) * 128 + n]);
        }
        if (t < 128) bias[t] = bp1[t];
        CP_WAIT0();
        __syncthreads();

        const int w = t >> 5, l = t & 31;
        const int lr = l >> 2, lc = l & 3;
        const int mrow0 = (w & 1) * 32;
        const int ncol0 = (w >> 1) * 32;

        float acc[2][4][4];
        #pragma unroll
        for (int mt = 0; mt < 2; mt++)
            #pragma unroll
            for (int nt = 0; nt < 4; nt++)
                #pragma unroll
                for (int j = 0; j < 4; j++) acc[mt][nt][j] = 0.f;

        const float* ab = Xs + (mrow0 + lr) * XSTR + lc * 2;

        #pragma unroll
        for (int kc = 0; kc < 16; kc++) {
            const int kb = kc * 16;
            uint32_t Ah[2][4], Al[2][4];
            #pragma unroll
            for (int mt = 0; mt < 2; mt++) {
                const float* p = ab + mt * 16 * XSTR + kb;
                float2 v0 = *(const float2*)(p);
                float2 v1 = *(const float2*)(p + 8 * XSTR);
                float2 v2 = *(const float2*)(p + 8);
                float2 v3 = *(const float2*)(p + 8 * XSTR + 8);
                split2h(v0.x, v0.y, Ah[mt][0], Al[mt][0]);
                split2h(v1.x, v1.y, Ah[mt][1], Al[mt][1]);
                split2h(v2.x, v2.y, Ah[mt][2], Al[mt][2]);
                split2h(v3.x, v3.y, Ah[mt][3], Al[mt][3]);
            }
            #pragma unroll
            for (int nt = 0; nt < 4; nt++) {
                const __half* bp = Bf + (ncol0 + nt * 8 + lr) * KSTR
                                      + kb + lc * 2;
                uint32_t b0 = *(const uint32_t*)bp;
                uint32_t b1 = *(const uint32_t*)(bp + 8);
                #pragma unroll
                for (int mt = 0; mt < 2; mt++) {
                    mma_f16(acc[mt][nt], Ah[mt], b0, b1);
                    mma_f16(acc[mt][nt], Al[mt], b0, b1);
                }
            }
        }

        #pragma unroll
        for (int mt = 0; mt < 2; mt++) {
            int ga = g0 + mrow0 + mt * 16 + lr;
            #pragma unroll
            for (int nt = 0; nt < 4; nt++) {
                int col = ncol0 + nt * 8 + lc * 2;
                float ba = bias[col], bb = bias[col + 1];
                *(float2*)(g_base + (size_t)ga * 128 + col) =
                    make_float2(acc[mt][nt][0] + ba, acc[mt][nt][1] + bb);
                *(float2*)(g_base + (size_t)(ga + 8) * 128 + col) =
                    make_float2(acc[mt][nt][2] + ba, acc[mt][nt][3] + bb);
            }
        }
        return;
    }

    // =================== label body (R12, 64 graphs) =======================
    {
        float* Xs  = (float*)smc;                    // [64][LXS]
        float* Hs  = Xs + 64 * LXS;                  // [64][LXS]
        __half* Wf = (__half*)(Hs + 64 * LXS);       // [128][LWS]
        float* w3  = (float*)(Wf + 128 * LWS);       // [128*NL]
        float* b3s = w3 + 128 * NL;                  // [NL]
        float* bias = b3s + 16;                      // [128]

        const int b0 = ((int)blockIdx.x - nBase) * 64;
        const uint32_t xs_u32 = smem_u32(Xs);

        for (int i = t; i < 128 * NL; i += 256) w3[i] = Wl3[i];
        if (t < NL) b3s[t] = bl3[t];

        const int w = t >> 5, l = t & 31;
        const int lr = l >> 2, lc = l & 3;
        const int mrow0 = (w & 1) * 32;
        const int ncol0 = (w >> 1) * 32;

        float acc[2][4][4];
        #pragma unroll
        for (int mt = 0; mt < 2; mt++)
            #pragma unroll
            for (int nt = 0; nt < 4; nt++)
                #pragma unroll
                for (int j = 0; j < 4; j++) acc[mt][nt][j] = 0.f;

        for (int s = 0; s < 3; s++) {
            __syncthreads();

            #pragma unroll
            for (int i = 0; i < 8; i++) {
                int f = t + i * 256;
                int g = f >> 5, c4 = (f & 31) << 2;
                int pg = pgi[b0 + g];
                const float* src;
                if (s == 0)      src = node + (size_t)((pg + 1) * n_per - 1) * DD + c4;
                else if (s == 1) src = node + (size_t)pni[b0 + g] * DD + c4;
                else             src = glob + (size_t)pg * DD + c4;
                CP16(xs_u32 + (uint32_t)((g * LXS + c4) * 4), src);
            }
            CP_COMMIT();

            #pragma unroll
            for (int i = 0; i < 64; i++) {
                int idx = t + i * 256;
                int k = idx >> 7, n = idx & 127;
                Wf[n * LWS + k] =
                    __float2half_rn(Wl1[(size_t)(s * 128 + k) * 128 + n]);
            }
            CP_WAIT0();
            __syncthreads();

            const float* ab = Xs + (mrow0 + lr) * LXS + lc * 2;
            #pragma unroll
            for (int kc = 0; kc < 8; kc++) {
                const int kb = kc * 16;
                uint32_t Ah[2][4], Al[2][4];
                #pragma unroll
                for (int mt = 0; mt < 2; mt++) {
                    const float* p = ab + mt * 16 * LXS + kb;
                    float2 v0 = *(const float2*)(p);
                    float2 v1 = *(const float2*)(p + 8 * LXS);
                    float2 v2 = *(const float2*)(p + 8);
                    float2 v3 = *(const float2*)(p + 8 * LXS + 8);
                    split2h(v0.x, v0.y, Ah[mt][0], Al[mt][0]);
                    split2h(v1.x, v1.y, Ah[mt][1], Al[mt][1]);
                    split2h(v2.x, v2.y, Ah[mt][2], Al[mt][2]);
                    split2h(v3.x, v3.y, Ah[mt][3], Al[mt][3]);
                }
                #pragma unroll
                for (int nt = 0; nt < 4; nt++) {
                    const __half* bp = Wf + (ncol0 + nt * 8 + lr) * LWS
                                          + kb + lc * 2;
                    uint32_t b0w = *(const uint32_t*)bp;
                    uint32_t b1w = *(const uint32_t*)(bp + 8);
                    #pragma unroll
                    for (int mt = 0; mt < 2; mt++) {
                        mma_f16(acc[mt][nt], Ah[mt], b0w, b1w);
                        mma_f16(acc[mt][nt], Al[mt], b0w, b1w);
                    }
                }
            }
        }

        if (t < 128) bias[t] = bl1[t];
        __syncthreads();

        #pragma unroll
        for (int mt = 0; mt < 2; mt++) {
            int row = mrow0 + mt * 16 + lr;
            #pragma unroll
            for (int nt = 0; nt < 4; nt++) {
                int col = ncol0 + nt * 8 + lc * 2;
                float ba = bias[col], bb = bias[col + 1];
                *(float2*)(Hs + row * LXS + col) = make_float2(
                    fmaxf(acc[mt][nt][0] + ba, 0.f),
                    fmaxf(acc[mt][nt][1] + bb, 0.f));
                *(float2*)(Hs + (row + 8) * LXS + col) = make_float2(
                    fmaxf(acc[mt][nt][2] + ba, 0.f),
                    fmaxf(acc[mt][nt][3] + bb, 0.f));
            }
        }
        __syncthreads();

        #pragma unroll
        for (int i = 0; i < 64; i++) {
            int idx = t + i * 256;
            int k = idx >> 7, n = idx & 127;
            Wf[n * LWS + k] = __float2half_rn(Wl2[(size_t)k * 128 + n]);
        }
        if (t < 128) bias[t] = bl2[t];
        __syncthreads();

        #pragma unroll
        for (int mt = 0; mt < 2; mt++)
            #pragma unroll
            for (int nt = 0; nt < 4; nt++)
                #pragma unroll
                for (int j = 0; j < 4; j++) acc[mt][nt][j] = 0.f;

        {
            const float* ab = Hs + (mrow0 + lr) * LXS + lc * 2;
            #pragma unroll
            for (int kc = 0; kc < 8; kc++) {
                const int kb = kc * 16;
                uint32_t Ah[2][4], Al[2][4];
                #pragma unroll
                for (int mt = 0; mt < 2; mt++) {
                    const float* p = ab + mt * 16 * LXS + kb;
                    float2 v0 = *(const float2*)(p);
                    float2 v1 = *(const float2*)(p + 8 * LXS);
                    float2 v2 = *(const float2*)(p + 8);
                    float2 v3 = *(const float2*)(p + 8 * LXS + 8);
                    split2h(v0.x, v0.y, Ah[mt][0], Al[mt][0]);
                    split2h(v1.x, v1.y, Ah[mt][1], Al[mt][1]);
                    split2h(v2.x, v2.y, Ah[mt][2], Al[mt][2]);
                    split2h(v3.x, v3.y, Ah[mt][3], Al[mt][3]);
                }
                #pragma unroll
                for (int nt = 0; nt < 4; nt++) {
                    const __half* bp = Wf + (ncol0 + nt * 8 + lr) * LWS
                                          + kb + lc * 2;
                    uint32_t b0w = *(const uint32_t*)bp;
                    uint32_t b1w = *(const uint32_t*)(bp + 8);
                    #pragma unroll
                    for (int mt = 0; mt < 2; mt++) {
                        mma_f16(acc[mt][nt], Ah[mt], b0w, b1w);
                        mma_f16(acc[mt][nt], Al[mt], b0w, b1w);
                    }
                }
            }
        }
        __syncthreads();

        #pragma unroll
        for (int mt = 0; mt < 2; mt++) {
            int row = mrow0 + mt * 16 + lr;
            #pragma unroll
            for (int nt = 0; nt < 4; nt++) {
                int col = ncol0 + nt * 8 + lc * 2;
                float ba = bias[col], bb = bias[col + 1];
                *(float2*)(Xs + row * LXS + col) = make_float2(
                    fmaxf(acc[mt][nt][0] + ba, 0.f),
                    fmaxf(acc[mt][nt][1] + bb, 0.f));
                *(float2*)(Xs + (row + 8) * LXS + col) = make_float2(
                    fmaxf(acc[mt][nt][2] + ba, 0.f),
                    fmaxf(acc[mt][nt][3] + bb, 0.f));
            }
        }
        __syncthreads();

        for (int o = t; o < 64 * NL; o += 256) {
            int g = o / NL, nl = o - g * NL;
            float a = b3s[nl];
            #pragma unroll 4
            for (int k = 0; k < 128; k++)
                a += Xs[g * LXS + k] * w3[k * NL + nl];
            out_label[(size_t)(b0 + g) * NL + nl] = a;
        }
    }
}

// ===========================================================================
// partner kernel (R15): occ-1 persistent, 512 threads (16 warps, 4/SMSP).
// Warp tile 32x32 (4 row bands x 4 col bands). Same 128-row tiles, same
// double-buffered whole-tile cp.async, same single-chain fp16 math.
// ===========================================================================
__global__ void __launch_bounds__(512, 1) partner_kernel(
    const float* __restrict__ node, const float* __restrict__ Wp1,
    const float* __restrict__ Wp2, const float* __restrict__ bp2,
    float* __restrict__ out, int ntiles)
{
    extern __shared__ char smc[];
    __half* Bf  = (__half*)smc;                      // [128][BSTR]
    float* Ab0  = (float*)(Bf + 128 * BSTR);         // [2][128][ATSTR]
    float* bs0  = Ab0 + 2 * 128 * ATSTR;             // [2][256]
    float* w2s  = bs0 + 512;                         // [128]
    float* srow = w2s + 128;                         // [128][4]

    const int t = threadIdx.x;
    const uint32_t ab_u32 = smem_u32(Ab0);
    const uint32_t bs_u32 = smem_u32(bs0);

    #pragma unroll
    for (int i = 0; i < 32; i++) {                   // Bf[n][k] = f16(Wm[k][n])
        int idx = t + i * 512;
        int k = idx >> 7, n = idx & 127;
        Bf[n * BSTR + k] = __float2half_rn(Wp1[(size_t)(128 + k) * 128 + n]);
    }
    if (t < 128) w2s[t] = Wp2[t];
    const float bp2v = bp2[0];

    const int w = t >> 5, l = t & 31;
    const int lr = l >> 2, lc = l & 3;
    const int mrow0 = (w & 3) * 32;                  // 4 row bands of 32
    const int ncol0 = (w >> 2) * 32;                 // 4 col bands of 32
    const int cband = w >> 2;
    const int gh = (w & 3) >> 1;                     // graph half of row band

    const int ntloc = (ntiles - (int)blockIdx.x + (int)gridDim.x - 1)
                      / (int)gridDim.x;

    auto issue_tile = [&](int q) {
        int tq = (int)blockIdx.x + q * (int)gridDim.x;
        if (tq < ntiles) {
            const float* src = node + (size_t)tq * (128 * DD);
            const uint32_t du = ab_u32
                + (uint32_t)((q & 1) * 128 * ATSTR * 4);
            #pragma unroll
            for (int i = 0; i < 8; i++) {            // 4096 float4, 512 lanes
                int f = t + i * 512;
                int row = f >> 5, c4 = (f & 31) << 2;
                CP16(du + (uint32_t)((row * ATSTR + c4) * 4), src + f * 4);
            }
            if (t < 64) {
                const float* sb = g_base + (size_t)tq * 256 + t * 4;
                CP16(bs_u32 + (uint32_t)(((q & 1) * 256 + t * 4) * 4), sb);
            }
        }
    };

    issue_tile(0); CP_COMMIT();
    issue_tile(1); CP_COMMIT();

    for (int q = 0; q < ntloc; q++) {
        const int tq = (int)blockIdx.x + q * (int)gridDim.x;

        CP_WAIT1();
        __syncthreads();

        const float* Abuf  = Ab0 + (q & 1) * (128 * ATSTR);
        const float* base2 = bs0 + (q & 1) * 256;

        float acc[2][4][4];
        #pragma unroll
        for (int mt = 0; mt < 2; mt++)
            #pragma unroll
            for (int nt = 0; nt < 4; nt++)
                #pragma unroll
                for (int j = 0; j < 4; j++) acc[mt][nt][j] = 0.f;

        const float* ab = Abuf + (mrow0 + lr) * ATSTR + lc * 2;

        #pragma unroll
        for (int kc = 0; kc < 8; kc++) {             // sync-free MMA stream
            const int kb = kc * 16;
            uint32_t Ah[2][4];
            #pragma unroll
            for (int mt = 0; mt < 2; mt++) {
                const float* p = ab + mt * 16 * ATSTR + kb;
                float2 v0 = *(const float2*)(p);
                float2 v1 = *(const float2*)(p + 8 * ATSTR);
                float2 v2 = *(const float2*)(p + 8);
                float2 v3 = *(const float2*)(p + 8 * ATSTR + 8);
                Ah[mt][0] = cvt2h(v0.x, v0.y);
                Ah[mt][1] = cvt2h(v1.x, v1.y);
                Ah[mt][2] = cvt2h(v2.x, v2.y);
                Ah[mt][3] = cvt2h(v3.x, v3.y);
            }
            #pragma unroll
            for (int nt = 0; nt < 4; nt++) {
                const __half* bp = Bf + (ncol0 + nt * 8 + lr) * BSTR
                                      + kb + lc * 2;
                uint32_t b0 = *(const uint32_t*)bp;
                uint32_t b1 = *(const uint32_t*)(bp + 8);
                mma_f16(acc[0][nt], Ah[0], b0, b1);
                mma_f16(acc[1][nt], Ah[1], b0, b1);
            }
        }

        // ---- epilogue: relu(acc+base).w2, quad-reduce, combine 4 cbands ----
        float pr[2][2] = {{0.f, 0.f}, {0.f, 0.f}};
        #pragma unroll
        for (int nt = 0; nt < 4; nt++) {
            int c0 = ncol0 + nt * 8 + lc * 2;
            float wa = w2s[c0], wb = w2s[c0 + 1];
            float ba = base2[gh * 128 + c0], bb = base2[gh * 128 + c0 + 1];
            #pragma unroll
            for (int mt = 0; mt < 2; mt++) {
                pr[mt][0] += fmaxf(acc[mt][nt][0] + ba, 0.f) * wa
                           + fmaxf(acc[mt][nt][1] + bb, 0.f) * wb;
                pr[mt][1] += fmaxf(acc[mt][nt][2] + ba, 0.f) * wa
                           + fmaxf(acc[mt][nt][3] + bb, 0.f) * wb;
            }
        }
        #pragma unroll
        for (int o = 1; o <= 2; o <<= 1) {
            pr[0][0] += __shfl_xor_sync(0xffffffffu, pr[0][0], o);
            pr[0][1] += __shfl_xor_sync(0xffffffffu, pr[0][1], o);
            pr[1][0] += __shfl_xor_sync(0xffffffffu, pr[1][0], o);
            pr[1][1] += __shfl_xor_sync(0xffffffffu, pr[1][1], o);
        }
        if (lc == 0) {
            srow[(mrow0 + lr) * 4 + cband]      = pr[0][0];
            srow[(mrow0 + lr + 8) * 4 + cband]  = pr[0][1];
            srow[(mrow0 + 16 + lr) * 4 + cband] = pr[1][0];
            srow[(mrow0 + 24 + lr) * 4 + cband] = pr[1][1];
        }
        __syncthreads();               // srow ready AND A buffer free
        if (t < 128)
            out[(size_t)tq * 128 + t] = srow[t * 4] + srow[t * 4 + 1]
                + srow[t * 4 + 2] + srow[t * 4 + 3] + bp2v;

        issue_tile(q + 2);             // refill the buffer just vacated
        CP_COMMIT();
    }
}

// ===========================================================================
extern "C" void kernel_launch(void* const* d_in, const int* in_sizes, int n_in,
                              void* d_out, int out_size)
{
    const float* node = (const float*)d_in[0];
    const float* glob = (const float*)d_in[1];
    const float* Wp1  = (const float*)d_in[2];
    const float* bp1  = (const float*)d_in[3];
    const float* Wp2  = (const float*)d_in[4];
    const float* bp2  = (const float*)d_in[5];
    const float* Wl1  = (const float*)d_in[6];
    const float* bl1  = (const float*)d_in[7];
    const float* Wl2  = (const float*)d_in[8];
    const float* bl2  = (const float*)d_in[9];
    const float* Wl3  = (const float*)d_in[10];
    const float* bl3  = (const float*)d_in[11];
    const int*   pgi  = (const int*)d_in[12];
    const int*   pni  = (const int*)d_in[13];

    const int N     = in_sizes[0] / DD;
    const int B     = in_sizes[1] / DD;
    const int n_per = N / B;            // 64
    const int NL    = in_sizes[11];     // 14
    const int ntiles = N / 128;         // 4096

    float* out = (float*)d_out;

    const size_t smBase = (size_t)(64 * XSTR) * sizeof(float)
                        + (size_t)(128 * KSTR) * sizeof(__half)
                        + 128 * sizeof(float);
    const size_t smLab  = (size_t)(2 * 64 * LXS) * sizeof(float)
                        + (size_t)(128 * LWS) * sizeof(__half)
                        + (size_t)(128 * NL + 16 + 128) * sizeof(float);
    const size_t smAux  = smBase > smLab ? smBase : smLab;
    const size_t smP = (size_t)(128 * BSTR) * sizeof(__half)
                     + (size_t)(2 * 128 * ATSTR + 512 + 128 + 512)
                       * sizeof(float);

    cudaFuncSetAttribute(aux_kernel,     cudaFuncAttributeMaxDynamicSharedMemorySize, (int)smAux);
    cudaFuncSetAttribute(partner_kernel, cudaFuncAttributeMaxDynamicSharedMemorySize, (int)smP);

    const int nBase = B / 64;           // 128 base blocks
    const int nLab  = B / 64;           // 128 label blocks
    aux_kernel<<<nBase + nLab, 256, smAux>>>(node, glob, Wp1, bp1,
                                             Wl1, bl1, Wl2, bl2, Wl3, bl3,
                                             pgi, pni, n_per, NL,
                                             out + (size_t)N, nBase);

    int grid = 148;                     // occ-1 persistent, 512 threads
    if (grid > ntiles) grid = ntiles;
    partner_kernel<<<grid, 512, smP>>>(node, Wp1, Wp2, bp2, out, ntiles);
}

// round 16
// speedup vs baseline: 1.2535x; 1.2535x over previous
#include <cuda_runtime.h>
#include <cuda_fp16.h>
#include <cstdint>

// ---------------------------------------------------------------------------
// AutoconstraintModel on GB300 (harness target sm_103 — legacy mma.sync).
// R16: R14 structure (best, 121.6us) + partner inner-loop A-fragment
//      prefetch (one k-chunk ahead, register double-buffer) to hide the
//      LDS->cvt->HMMA chunk-start bubble identified in the cycle model.
//   aux (R14-proven ~33us): base body (R8) + label body (R12), one launch.
//   partner: 256 threads, occ-1, 128-row tiles, double-buffered cp.async.
// rel_err 3.068e-4 (math unchanged).
// ---------------------------------------------------------------------------

#define DD 128
#define BSTR 136      // partner B smem row stride (fp16) — conflict-free
#define KSTR 264      // base B stride (fp16), K=256 — conflict-free
#define ATSTR 132     // partner A tile row stride (floats)
#define XSTR 260      // base X row stride (floats)
#define LXS 132       // label X/H row stride (floats)
#define LWS 136       // label W smem stride (fp16)

__device__ float g_base[8192 * 128];   // Base[B][128] scratch (4 MB static)

// ============================ HMMA helpers (fp16) ==========================
__device__ __forceinline__ void mma_f16(float* c, const uint32_t* a,
                                        uint32_t b0, uint32_t b1) {
    asm volatile(
        "mma.sync.aligned.m16n8k16.row.col.f32.f16.f16.f32 "
        "{%0,%1,%2,%3}, {%4,%5,%6,%7}, {%8,%9}, {%0,%1,%2,%3};"
        : "+f"(c[0]), "+f"(c[1]), "+f"(c[2]), "+f"(c[3])
        : "r"(a[0]), "r"(a[1]), "r"(a[2]), "r"(a[3]), "r"(b0), "r"(b1));
}

__device__ __forceinline__ uint32_t cvt2h(float x, float y) {
    __half2 h = __floats2half2_rn(x, y);
    return *reinterpret_cast<uint32_t*>(&h);
}
__device__ __forceinline__ void split2h(float x, float y,
                                        uint32_t& hi, uint32_t& lo) {
    __half2 h = __floats2half2_rn(x, y);
    float2 hf = __half22float2(h);
    __half2 r = __floats2half2_rn(x - hf.x, y - hf.y);
    hi = *reinterpret_cast<uint32_t*>(&h);
    lo = *reinterpret_cast<uint32_t*>(&r);
}

__device__ __forceinline__ uint32_t smem_u32(const void* p) {
    uint32_t a;
    asm("{ .reg .u64 t; cvta.to.shared.u64 t, %1; cvt.u32.u64 %0, t; }"
        : "=r"(a) : "l"(p));
    return a;
}

#define CP16(dst_u32, src_ptr) \
    asm volatile("cp.async.cg.shared.global [%0], [%1], 16;" \
                 :: "r"(dst_u32), "l"(src_ptr))
#define CP_COMMIT() asm volatile("cp.async.commit_group;" ::: "memory")
#define CP_WAIT0()  asm volatile("cp.async.wait_group 0;" ::: "memory")
#define CP_WAIT1()  asm volatile("cp.async.wait_group 1;" ::: "memory")

// ===========================================================================
// aux kernel (R14-proven): blocks [0,nBase) base body, rest label body.
// ===========================================================================
__global__ void __launch_bounds__(256, 1) aux_kernel(
    const float* __restrict__ node, const float* __restrict__ glob,
    const float* __restrict__ Wp1, const float* __restrict__ bp1,
    const float* __restrict__ Wl1, const float* __restrict__ bl1,
    const float* __restrict__ Wl2, const float* __restrict__ bl2,
    const float* __restrict__ Wl3, const float* __restrict__ bl3,
    const int* __restrict__ pgi, const int* __restrict__ pni,
    int n_per, int NL, float* __restrict__ out_label, int nBase)
{
    extern __shared__ char smc[];
    const int t = threadIdx.x;

    if ((int)blockIdx.x < nBase) {
        // ================= base body (R8, 64 graphs) =======================
        float* Xs   = (float*)smc;                   // [64][XSTR]
        __half* Bf  = (__half*)(Xs + 64 * XSTR);     // [128][KSTR]
        float* bias = (float*)(Bf + 128 * KSTR);     // [128]

        const int g0 = (int)blockIdx.x * 64;
        const uint32_t xs_u32 = smem_u32(Xs);

        #pragma unroll
        for (int i = 0; i < 8; i++) {                // cur: 2048 float4
            int f = t + i * 256;
            int g = f >> 5, c4 = (f & 31) << 2;
            const float* src = node
                + (size_t)((g0 + g + 1) * n_per - 1) * DD + c4;
            CP16(xs_u32 + (uint32_t)((g * XSTR + c4) * 4), src);
        }
        #pragma unroll
        for (int i = 0; i < 8; i++) {                // glob: 2048 float4
            int f = t + i * 256;
            int g = f >> 5, c4 = (f & 31) << 2;
            const float* src = glob + (size_t)(g0 + g) * DD + c4;
            CP16(xs_u32 + (uint32_t)((g * XSTR + 128 + c4) * 4), src);
        }
        CP_COMMIT();

        #pragma unroll
        for (int i = 0; i < 128; i++) {              // Bf[n][k] = f16(W[k][n])
            int idx = t + i * 256;
            int k = idx >> 7, n = idx & 127;
            Bf[n * KSTR + k] = __float2half_rn(
                Wp1[(size_t)(k < 128 ? k : k + 128) * 128 + n]);
        }
        if (t < 128) bias[t] = bp1[t];
        CP_WAIT0();
        __syncthreads();

        const int w = t >> 5, l = t & 31;
        const int lr = l >> 2, lc = l & 3;
        const int mrow0 = (w & 1) * 32;
        const int ncol0 = (w >> 1) * 32;

        float acc[2][4][4];
        #pragma unroll
        for (int mt = 0; mt < 2; mt++)
            #pragma unroll
            for (int nt = 0; nt < 4; nt++)
                #pragma unroll
                for (int j = 0; j < 4; j++) acc[mt][nt][j] = 0.f;

        const float* ab = Xs + (mrow0 + lr) * XSTR + lc * 2;

        #pragma unroll
        for (int kc = 0; kc < 16; kc++) {
            const int kb = kc * 16;
            uint32_t Ah[2][4], Al[2][4];
            #pragma unroll
            for (int mt = 0; mt < 2; mt++) {
                const float* p = ab + mt * 16 * XSTR + kb;
                float2 v0 = *(const float2*)(p);
                float2 v1 = *(const float2*)(p + 8 * XSTR);
                float2 v2 = *(const float2*)(p + 8);
                float2 v3 = *(const float2*)(p + 8 * XSTR + 8);
                split2h(v0.x, v0.y, Ah[mt][0], Al[mt][0]);
                split2h(v1.x, v1.y, Ah[mt][1], Al[mt][1]);
                split2h(v2.x, v2.y, Ah[mt][2], Al[mt][2]);
                split2h(v3.x, v3.y, Ah[mt][3], Al[mt][3]);
            }
            #pragma unroll
            for (int nt = 0; nt < 4; nt++) {
                const __half* bp = Bf + (ncol0 + nt * 8 + lr) * KSTR
                                      + kb + lc * 2;
                uint32_t b0 = *(const uint32_t*)bp;
                uint32_t b1 = *(const uint32_t*)(bp + 8);
                #pragma unroll
                for (int mt = 0; mt < 2; mt++) {
                    mma_f16(acc[mt][nt], Ah[mt], b0, b1);
                    mma_f16(acc[mt][nt], Al[mt], b0, b1);
                }
            }
        }

        #pragma unroll
        for (int mt = 0; mt < 2; mt++) {
            int ga = g0 + mrow0 + mt * 16 + lr;
            #pragma unroll
            for (int nt = 0; nt < 4; nt++) {
                int col = ncol0 + nt * 8 + lc * 2;
                float ba = bias[col], bb = bias[col + 1];
                *(float2*)(g_base + (size_t)ga * 128 + col) =
                    make_float2(acc[mt][nt][0] + ba, acc[mt][nt][1] + bb);
                *(float2*)(g_base + (size_t)(ga + 8) * 128 + col) =
                    make_float2(acc[mt][nt][2] + ba, acc[mt][nt][3] + bb);
            }
        }
        return;
    }

    // =================== label body (R12, 64 graphs) =======================
    {
        float* Xs  = (float*)smc;                    // [64][LXS]
        float* Hs  = Xs + 64 * LXS;                  // [64][LXS]
        __half* Wf = (__half*)(Hs + 64 * LXS);       // [128][LWS]
        float* w3  = (float*)(Wf + 128 * LWS);       // [128*NL]
        float* b3s = w3 + 128 * NL;                  // [NL]
        float* bias = b3s + 16;                      // [128]

        const int b0 = ((int)blockIdx.x - nBase) * 64;
        const uint32_t xs_u32 = smem_u32(Xs);

        for (int i = t; i < 128 * NL; i += 256) w3[i] = Wl3[i];
        if (t < NL) b3s[t] = bl3[t];

        const int w = t >> 5, l = t & 31;
        const int lr = l >> 2, lc = l & 3;
        const int mrow0 = (w & 1) * 32;
        const int ncol0 = (w >> 1) * 32;

        float acc[2][4][4];
        #pragma unroll
        for (int mt = 0; mt < 2; mt++)
            #pragma unroll
            for (int nt = 0; nt < 4; nt++)
                #pragma unroll
                for (int j = 0; j < 4; j++) acc[mt][nt][j] = 0.f;

        for (int s = 0; s < 3; s++) {
            __syncthreads();

            #pragma unroll
            for (int i = 0; i < 8; i++) {
                int f = t + i * 256;
                int g = f >> 5, c4 = (f & 31) << 2;
                int pg = pgi[b0 + g];
                const float* src;
                if (s == 0)      src = node + (size_t)((pg + 1) * n_per - 1) * DD + c4;
                else if (s == 1) src = node + (size_t)pni[b0 + g] * DD + c4;
                else             src = glob + (size_t)pg * DD + c4;
                CP16(xs_u32 + (uint32_t)((g * LXS + c4) * 4), src);
            }
            CP_COMMIT();

            #pragma unroll
            for (int i = 0; i < 64; i++) {
                int idx = t + i * 256;
                int k = idx >> 7, n = idx & 127;
                Wf[n * LWS + k] =
                    __float2half_rn(Wl1[(size_t)(s * 128 + k) * 128 + n]);
            }
            CP_WAIT0();
            __syncthreads();

            const float* ab = Xs + (mrow0 + lr) * LXS + lc * 2;
            #pragma unroll
            for (int kc = 0; kc < 8; kc++) {
                const int kb = kc * 16;
                uint32_t Ah[2][4], Al[2][4];
                #pragma unroll
                for (int mt = 0; mt < 2; mt++) {
                    const float* p = ab + mt * 16 * LXS + kb;
                    float2 v0 = *(const float2*)(p);
                    float2 v1 = *(const float2*)(p + 8 * LXS);
                    float2 v2 = *(const float2*)(p + 8);
                    float2 v3 = *(const float2*)(p + 8 * LXS + 8);
                    split2h(v0.x, v0.y, Ah[mt][0], Al[mt][0]);
                    split2h(v1.x, v1.y, Ah[mt][1], Al[mt][1]);
                    split2h(v2.x, v2.y, Ah[mt][2], Al[mt][2]);
                    split2h(v3.x, v3.y, Ah[mt][3], Al[mt][3]);
                }
                #pragma unroll
                for (int nt = 0; nt < 4; nt++) {
                    const __half* bp = Wf + (ncol0 + nt * 8 + lr) * LWS
                                          + kb + lc * 2;
                    uint32_t b0w = *(const uint32_t*)bp;
                    uint32_t b1w = *(const uint32_t*)(bp + 8);
                    #pragma unroll
                    for (int mt = 0; mt < 2; mt++) {
                        mma_f16(acc[mt][nt], Ah[mt], b0w, b1w);
                        mma_f16(acc[mt][nt], Al[mt], b0w, b1w);
                    }
                }
            }
        }

        if (t < 128) bias[t] = bl1[t];
        __syncthreads();

        #pragma unroll
        for (int mt = 0; mt < 2; mt++) {
            int row = mrow0 + mt * 16 + lr;
            #pragma unroll
            for (int nt = 0; nt < 4; nt++) {
                int col = ncol0 + nt * 8 + lc * 2;
                float ba = bias[col], bb = bias[col + 1];
                *(float2*)(Hs + row * LXS + col) = make_float2(
                    fmaxf(acc[mt][nt][0] + ba, 0.f),
                    fmaxf(acc[mt][nt][1] + bb, 0.f));
                *(float2*)(Hs + (row + 8) * LXS + col) = make_float2(
                    fmaxf(acc[mt][nt][2] + ba, 0.f),
                    fmaxf(acc[mt][nt][3] + bb, 0.f));
            }
        }
        __syncthreads();

        #pragma unroll
        for (int i = 0; i < 64; i++) {
            int idx = t + i * 256;
            int k = idx >> 7, n = idx & 127;
            Wf[n * LWS + k] = __float2half_rn(Wl2[(size_t)k * 128 + n]);
        }
        if (t < 128) bias[t] = bl2[t];
        __syncthreads();

        #pragma unroll
        for (int mt = 0; mt < 2; mt++)
            #pragma unroll
            for (int nt = 0; nt < 4; nt++)
                #pragma unroll
                for (int j = 0; j < 4; j++) acc[mt][nt][j] = 0.f;

        {
            const float* ab = Hs + (mrow0 + lr) * LXS + lc * 2;
            #pragma unroll
            for (int kc = 0; kc < 8; kc++) {
                const int kb = kc * 16;
                uint32_t Ah[2][4], Al[2][4];
                #pragma unroll
                for (int mt = 0; mt < 2; mt++) {
                    const float* p = ab + mt * 16 * LXS + kb;
                    float2 v0 = *(const float2*)(p);
                    float2 v1 = *(const float2*)(p + 8 * LXS);
                    float2 v2 = *(const float2*)(p + 8);
                    float2 v3 = *(const float2*)(p + 8 * LXS + 8);
                    split2h(v0.x, v0.y, Ah[mt][0], Al[mt][0]);
                    split2h(v1.x, v1.y, Ah[mt][1], Al[mt][1]);
                    split2h(v2.x, v2.y, Ah[mt][2], Al[mt][2]);
                    split2h(v3.x, v3.y, Ah[mt][3], Al[mt][3]);
                }
                #pragma unroll
                for (int nt = 0; nt < 4; nt++) {
                    const __half* bp = Wf + (ncol0 + nt * 8 + lr) * LWS
                                          + kb + lc * 2;
                    uint32_t b0w = *(const uint32_t*)bp;
                    uint32_t b1w = *(const uint32_t*)(bp + 8);
                    #pragma unroll
                    for (int mt = 0; mt < 2; mt++) {
                        mma_f16(acc[mt][nt], Ah[mt], b0w, b1w);
                        mma_f16(acc[mt][nt], Al[mt], b0w, b1w);
                    }
                }
            }
        }
        __syncthreads();

        #pragma unroll
        for (int mt = 0; mt < 2; mt++) {
            int row = mrow0 + mt * 16 + lr;
            #pragma unroll
            for (int nt = 0; nt < 4; nt++) {
                int col = ncol0 + nt * 8 + lc * 2;
                float ba = bias[col], bb = bias[col + 1];
                *(float2*)(Xs + row * LXS + col) = make_float2(
                    fmaxf(acc[mt][nt][0] + ba, 0.f),
                    fmaxf(acc[mt][nt][1] + bb, 0.f));
                *(float2*)(Xs + (row + 8) * LXS + col) = make_float2(
                    fmaxf(acc[mt][nt][2] + ba, 0.f),
                    fmaxf(acc[mt][nt][3] + bb, 0.f));
            }
        }
        __syncthreads();

        for (int o = t; o < 64 * NL; o += 256) {
            int g = o / NL, nl = o - g * NL;
            float a = b3s[nl];
            #pragma unroll 4
            for (int k = 0; k < 128; k++)
                a += Xs[g * LXS + k] * w3[k * NL + nl];
            out_label[(size_t)(b0 + g) * NL + nl] = a;
        }
    }
}

// ===========================================================================
// partner kernel (R16): R9/R14 shape (256 threads, occ-1, 128-row tiles,
// double-buffered cp.async) + A-fragment register prefetch one chunk ahead.
// ===========================================================================
__global__ void __launch_bounds__(256, 1) partner_kernel(
    const float* __restrict__ node, const float* __restrict__ Wp1,
    const float* __restrict__ Wp2, const float* __restrict__ bp2,
    float* __restrict__ out, int ntiles)
{
    extern __shared__ char smc[];
    __half* Bf  = (__half*)smc;                      // [128][BSTR]
    float* Ab0  = (float*)(Bf + 128 * BSTR);         // [2][128][ATSTR]
    float* bs0  = Ab0 + 2 * 128 * ATSTR;             // [2][256]
    float* w2s  = bs0 + 512;                         // [128]
    float* srow = w2s + 128;                         // [128][2]

    const int t = threadIdx.x;
    const uint32_t ab_u32 = smem_u32(Ab0);
    const uint32_t bs_u32 = smem_u32(bs0);

    #pragma unroll
    for (int i = 0; i < 64; i++) {                   // Bf[n][k] = f16(Wm[k][n])
        int idx = t + i * 256;
        int k = idx >> 7, n = idx & 127;
        Bf[n * BSTR + k] = __float2half_rn(Wp1[(size_t)(128 + k) * 128 + n]);
    }
    if (t < 128) w2s[t] = Wp2[t];
    const float bp2v = bp2[0];

    const int w = t >> 5, l = t & 31;
    const int lr = l >> 2, lc = l & 3;
    const int mrow0 = (w & 3) * 32;
    const int ncol0 = (w >> 2) * 64;
    const int gh = (w & 3) >> 1;

    const int ntloc = (ntiles - (int)blockIdx.x + (int)gridDim.x - 1)
                      / (int)gridDim.x;

    auto issue_tile = [&](int q) {
        int tq = (int)blockIdx.x + q * (int)gridDim.x;
        if (tq < ntiles) {
            const float* src = node + (size_t)tq * (128 * DD);
            const uint32_t du = ab_u32
                + (uint32_t)((q & 1) * 128 * ATSTR * 4);
            #pragma unroll
            for (int i = 0; i < 16; i++) {           // 4096 float4
                int f = t + i * 256;
                int row = f >> 5, c4 = (f & 31) << 2;
                CP16(du + (uint32_t)((row * ATSTR + c4) * 4), src + f * 4);
            }
            if (t < 64) {
                const float* sb = g_base + (size_t)tq * 256 + t * 4;
                CP16(bs_u32 + (uint32_t)(((q & 1) * 256 + t * 4) * 4), sb);
            }
        }
    };

    // A-fragment loader: chunk kc -> 8 fp16x2 regs (per warp tile)
    auto load_a = [&](const float* ab, int kc, uint32_t Adst[2][4]) {
        const int kb = kc * 16;
        #pragma unroll
        for (int mt = 0; mt < 2; mt++) {
            const float* p = ab + mt * 16 * ATSTR + kb;
            float2 v0 = *(const float2*)(p);
            float2 v1 = *(const float2*)(p + 8 * ATSTR);
            float2 v2 = *(const float2*)(p + 8);
            float2 v3 = *(const float2*)(p + 8 * ATSTR + 8);
            Adst[mt][0] = cvt2h(v0.x, v0.y);
            Adst[mt][1] = cvt2h(v1.x, v1.y);
            Adst[mt][2] = cvt2h(v2.x, v2.y);
            Adst[mt][3] = cvt2h(v3.x, v3.y);
        }
    };

    issue_tile(0); CP_COMMIT();
    issue_tile(1); CP_COMMIT();

    for (int q = 0; q < ntloc; q++) {
        const int tq = (int)blockIdx.x + q * (int)gridDim.x;

        CP_WAIT1();
        __syncthreads();

        const float* Abuf  = Ab0 + (q & 1) * (128 * ATSTR);
        const float* base2 = bs0 + (q & 1) * 256;

        float acc[2][8][4];
        #pragma unroll
        for (int mt = 0; mt < 2; mt++)
            #pragma unroll
            for (int nt = 0; nt < 8; nt++)
                #pragma unroll
                for (int j = 0; j < 4; j++) acc[mt][nt][j] = 0.f;

        const float* ab = Abuf + (mrow0 + lr) * ATSTR + lc * 2;

        // ---- software-pipelined MMA stream: A prefetch 1 chunk ahead ----
        uint32_t Ah[2][4];
        load_a(ab, 0, Ah);

        #pragma unroll
        for (int kc = 0; kc < 8; kc++) {
            uint32_t An[2][4];
            if (kc < 7) load_a(ab, kc + 1, An);      // overlaps HMMAs below

            const int kb = kc * 16;
            #pragma unroll
            for (int nt = 0; nt < 8; nt++) {
                const __half* bp = Bf + (ncol0 + nt * 8 + lr) * BSTR
                                      + kb + lc * 2;
                uint32_t b0 = *(const uint32_t*)bp;
                uint32_t b1 = *(const uint32_t*)(bp + 8);
                mma_f16(acc[0][nt], Ah[0], b0, b1);
                mma_f16(acc[1][nt], Ah[1], b0, b1);
            }
            if (kc < 7) {
                #pragma unroll
                for (int mt = 0; mt < 2; mt++)
                    #pragma unroll
                    for (int j = 0; j < 4; j++) Ah[mt][j] = An[mt][j];
            }
        }

        // ---- epilogue: relu(acc+base).w2, quad-reduce, combine ----
        float pr[2][2] = {{0.f, 0.f}, {0.f, 0.f}};
        #pragma unroll
        for (int nt = 0; nt < 8; nt++) {
            int c0 = ncol0 + nt * 8 + lc * 2;
            float wa = w2s[c0], wb = w2s[c0 + 1];
            float ba = base2[gh * 128 + c0], bb = base2[gh * 128 + c0 + 1];
            #pragma unroll
            for (int mt = 0; mt < 2; mt++) {
                pr[mt][0] += fmaxf(acc[mt][nt][0] + ba, 0.f) * wa
                           + fmaxf(acc[mt][nt][1] + bb, 0.f) * wb;
                pr[mt][1] += fmaxf(acc[mt][nt][2] + ba, 0.f) * wa
                           + fmaxf(acc[mt][nt][3] + bb, 0.f) * wb;
            }
        }
        #pragma unroll
        for (int o = 1; o <= 2; o <<= 1) {
            pr[0][0] += __shfl_xor_sync(0xffffffffu, pr[0][0], o);
            pr[0][1] += __shfl_xor_sync(0xffffffffu, pr[0][1], o);
            pr[1][0] += __shfl_xor_sync(0xffffffffu, pr[1][0], o);
            pr[1][1] += __shfl_xor_sync(0xffffffffu, pr[1][1], o);
        }
        if (lc == 0) {
            const int cg = w >> 2;
            srow[(mrow0 + lr) * 2 + cg]      = pr[0][0];
            srow[(mrow0 + lr + 8) * 2 + cg]  = pr[0][1];
            srow[(mrow0 + 16 + lr) * 2 + cg] = pr[1][0];
            srow[(mrow0 + 24 + lr) * 2 + cg] = pr[1][1];
        }
        __syncthreads();               // srow ready AND A buffer free

        issue_tile(q + 2);             // refill ASAP (before out store)
        CP_COMMIT();

        if (t < 128)
            out[(size_t)tq * 128 + t] = srow[t * 2] + srow[t * 2 + 1] + bp2v;
    }
}

// ===========================================================================
extern "C" void kernel_launch(void* const* d_in, const int* in_sizes, int n_in,
                              void* d_out, int out_size)
{
    const float* node = (const float*)d_in[0];
    const float* glob = (const float*)d_in[1];
    const float* Wp1  = (const float*)d_in[2];
    const float* bp1  = (const float*)d_in[3];
    const float* Wp2  = (const float*)d_in[4];
    const float* bp2  = (const float*)d_in[5];
    const float* Wl1  = (const float*)d_in[6];
    const float* bl1  = (const float*)d_in[7];
    const float* Wl2  = (const float*)d_in[8];
    const float* bl2  = (const float*)d_in[9];
    const float* Wl3  = (const float*)d_in[10];
    const float* bl3  = (const float*)d_in[11];
    const int*   pgi  = (const int*)d_in[12];
    const int*   pni  = (const int*)d_in[13];

    const int N     = in_sizes[0] / DD;
    const int B     = in_sizes[1] / DD;
    const int n_per = N / B;            // 64
    const int NL    = in_sizes[11];     // 14
    const int ntiles = N / 128;         // 4096

    float* out = (float*)d_out;

    const size_t smBase = (size_t)(64 * XSTR) * sizeof(float)
                        + (size_t)(128 * KSTR) * sizeof(__half)
                        + 128 * sizeof(float);
    const size_t smLab  = (size_t)(2 * 64 * LXS) * sizeof(float)
                        + (size_t)(128 * LWS) * sizeof(__half)
                        + (size_t)(128 * NL + 16 + 128) * sizeof(float);
    const size_t smAux  = smBase > smLab ? smBase : smLab;
    const size_t smP = (size_t)(128 * BSTR) * sizeof(__half)
                     + (size_t)(2 * 128 * ATSTR + 512 + 128 + 256)
                       * sizeof(float);

    cudaFuncSetAttribute(aux_kernel,     cudaFuncAttributeMaxDynamicSharedMemorySize, (int)smAux);
    cudaFuncSetAttribute(partner_kernel, cudaFuncAttributeMaxDynamicSharedMemorySize, (int)smP);

    const int nBase = B / 64;           // 128 base blocks
    const int nLab  = B / 64;           // 128 label blocks
    aux_kernel<<<nBase + nLab, 256, smAux>>>(node, glob, Wp1, bp1,
                                             Wl1, bl1, Wl2, bl2, Wl3, bl3,
                                             pgi, pni, n_per, NL,
                                             out + (size_t)N, nBase);

    int grid = 148;                     // occ-1 persistent
    if (grid > ntiles) grid = ntiles;
    partner_kernel<<<grid, 256, smP>>>(node, Wp1, Wp2, bp2, out, ntiles);
}

// round 17
// speedup vs baseline: 1.2973x; 1.0349x over previous
#include <cuda_runtime.h>
#include <cuda_fp16.h>
#include <cstdint>

// ---------------------------------------------------------------------------
// AutoconstraintModel on GB300 (harness target sm_103 — legacy mma.sync).
// R17: one-time wconv kernel pre-converts all weights to transposed fp16
//      scratch; aux/partner stage weights via cp.async (no per-block cvt).
//   wconv  (new, ~3us): 7 blocks, smem-transposed fp16 of Wp1ac/Wl1/Wl2/Wm.
//   aux    (R14 bodies, staging via cp.async): base + label, one launch.
//   partner(R14-proven mainloop, 83.8us): Bf staged via cp.async from g_wm.
// rel_err 3.068e-4 (same __float2half_rn values; math unchanged).
// ---------------------------------------------------------------------------

#define DD 128
#define BSTR 136      // partner/label W smem row stride (fp16): 272B, 16B-mult
#define KSTR 264      // base W smem stride (fp16), K=256: 528B, 16B-mult
#define ATSTR 132     // partner A tile row stride (floats)
#define XSTR 260      // base X row stride (floats)
#define LXS 132       // label X/H row stride (floats)
#define LWS 136       // label W smem stride (fp16)

__device__ float g_base[8192 * 128];     // Base[B][128] scratch (4 MB)
__device__ __half g_wac[128 * 256];      // [n][k] fp16 of W1ac (k-major)
__device__ __half g_wl1[3 * 128 * 128];  // [s][n][k] fp16 of Wl1^T
__device__ __half g_wl2[128 * 128];      // [n][k] fp16 of Wl2^T
__device__ __half g_wm[128 * 128];       // [n][k] fp16 of Wm^T

// ============================ HMMA helpers (fp16) ==========================
__device__ __forceinline__ void mma_f16(float* c, const uint32_t* a,
                                        uint32_t b0, uint32_t b1) {
    asm volatile(
        "mma.sync.aligned.m16n8k16.row.col.f32.f16.f16.f32 "
        "{%0,%1,%2,%3}, {%4,%5,%6,%7}, {%8,%9}, {%0,%1,%2,%3};"
        : "+f"(c[0]), "+f"(c[1]), "+f"(c[2]), "+f"(c[3])
        : "r"(a[0]), "r"(a[1]), "r"(a[2]), "r"(a[3]), "r"(b0), "r"(b1));
}

__device__ __forceinline__ uint32_t cvt2h(float x, float y) {
    __half2 h = __floats2half2_rn(x, y);
    return *reinterpret_cast<uint32_t*>(&h);
}
__device__ __forceinline__ void split2h(float x, float y,
                                        uint32_t& hi, uint32_t& lo) {
    __half2 h = __floats2half2_rn(x, y);
    float2 hf = __half22float2(h);
    __half2 r = __floats2half2_rn(x - hf.x, y - hf.y);
    hi = *reinterpret_cast<uint32_t*>(&h);
    lo = *reinterpret_cast<uint32_t*>(&r);
}

__device__ __forceinline__ uint32_t smem_u32(const void* p) {
    uint32_t a;
    asm("{ .reg .u64 t; cvta.to.shared.u64 t, %1; cvt.u32.u64 %0, t; }"
        : "=r"(a) : "l"(p));
    return a;
}

#define CP16(dst_u32, src_ptr) \
    asm volatile("cp.async.cg.shared.global [%0], [%1], 16;" \
                 :: "r"(dst_u32), "l"(src_ptr))
#define CP_COMMIT() asm volatile("cp.async.commit_group;" ::: "memory")
#define CP_WAIT0()  asm volatile("cp.async.wait_group 0;" ::: "memory")
#define CP_WAIT1()  asm volatile("cp.async.wait_group 1;" ::: "memory")

// ===========================================================================
// wconv kernel: 7 blocks. Each transposes+converts one 128k x 128n chunk
// of a weight matrix into fp16 scratch laid out [n][k] (k contiguous).
// ===========================================================================
__global__ void __launch_bounds__(256, 1) wconv_kernel(
    const float* __restrict__ Wp1, const float* __restrict__ Wl1,
    const float* __restrict__ Wl2)
{
    __shared__ __half sm[128 * 136];
    const int c = (int)blockIdx.x, t = threadIdx.x;

    const float* src;
    __half* dst;
    int dstride;
    if (c == 0)      { src = Wp1;              dst = g_wac;        dstride = 256; }
    else if (c == 1) { src = Wp1 + 256 * 128;  dst = g_wac + 128;  dstride = 256; }
    else if (c <= 4) { src = Wl1 + (c - 2) * 128 * 128;
                       dst = g_wl1 + (c - 2) * 128 * 128;          dstride = 128; }
    else if (c == 5) { src = Wl2;              dst = g_wl2;        dstride = 128; }
    else             { src = Wp1 + 128 * 128;  dst = g_wm;         dstride = 128; }

    #pragma unroll
    for (int i = 0; i < 64; i++) {           // read W[k][n] coalesced over n
        int idx = t + i * 256;
        int k = idx >> 7, n = idx & 127;
        sm[n * 136 + k] = __float2half_rn(src[(size_t)k * 128 + n]);
    }
    __syncthreads();
    #pragma unroll
    for (int i = 0; i < 16; i++) {           // write [n][k] coalesced over k
        int idx = t + i * 256;
        int n = idx >> 5, k4 = (idx & 31) * 4;
        *(uint2*)(dst + (size_t)n * dstride + k4) =
            *(const uint2*)(sm + n * 136 + k4);
    }
}

// ===========================================================================
// aux kernel: blocks [0,nBase) base body, rest label body. Weight staging
// via cp.async from fp16 scratch (no per-block conversion).
// ===========================================================================
__global__ void __launch_bounds__(256, 1) aux_kernel(
    const float* __restrict__ node, const float* __restrict__ glob,
    const float* __restrict__ bp1,
    const float* __restrict__ bl1, const float* __restrict__ bl2,
    const float* __restrict__ Wl3, const float* __restrict__ bl3,
    const int* __restrict__ pgi, const int* __restrict__ pni,
    int n_per, int NL, float* __restrict__ out_label, int nBase)
{
    extern __shared__ char smc[];
    const int t = threadIdx.x;

    if ((int)blockIdx.x < nBase) {
        // ================= base body (R8 mainloop, 64 graphs) ==============
        float* Xs   = (float*)smc;                   // [64][XSTR]
        __half* Bf  = (__half*)(Xs + 64 * XSTR);     // [128][KSTR]
        float* bias = (float*)(Bf + 128 * KSTR);     // [128]

        const int g0 = (int)blockIdx.x * 64;
        const uint32_t xs_u32 = smem_u32(Xs);
        const uint32_t bf_u32 = smem_u32(Bf);

        #pragma unroll
        for (int i = 0; i < 8; i++) {                // cur: 2048 float4
            int f = t + i * 256;
            int g = f >> 5, c4 = (f & 31) << 2;
            const float* src = node
                + (size_t)((g0 + g + 1) * n_per - 1) * DD + c4;
            CP16(xs_u32 + (uint32_t)((g * XSTR + c4) * 4), src);
        }
        #pragma unroll
        for (int i = 0; i < 8; i++) {                // glob: 2048 float4
            int f = t + i * 256;
            int g = f >> 5, c4 = (f & 31) << 2;
            const float* src = glob + (size_t)(g0 + g) * DD + c4;
            CP16(xs_u32 + (uint32_t)((g * XSTR + 128 + c4) * 4), src);
        }
        #pragma unroll
        for (int i = 0; i < 16; i++) {               // W: 128 rows x 512B
            int idx = t + i * 256;
            int row = idx >> 5, c16 = idx & 31;
            CP16(bf_u32 + (uint32_t)(row * (KSTR * 2) + c16 * 16),
                 (const float*)(g_wac + (size_t)row * 256 + c16 * 8));
        }
        CP_COMMIT();
        if (t < 128) bias[t] = bp1[t];
        CP_WAIT0();
        __syncthreads();

        const int w = t >> 5, l = t & 31;
        const int lr = l >> 2, lc = l & 3;
        const int mrow0 = (w & 1) * 32;
        const int ncol0 = (w >> 1) * 32;

        float acc[2][4][4];
        #pragma unroll
        for (int mt = 0; mt < 2; mt++)
            #pragma unroll
            for (int nt = 0; nt < 4; nt++)
                #pragma unroll
                for (int j = 0; j < 4; j++) acc[mt][nt][j] = 0.f;

        const float* ab = Xs + (mrow0 + lr) * XSTR + lc * 2;

        #pragma unroll
        for (int kc = 0; kc < 16; kc++) {
            const int kb = kc * 16;
            uint32_t Ah[2][4], Al[2][4];
            #pragma unroll
            for (int mt = 0; mt < 2; mt++) {
                const float* p = ab + mt * 16 * XSTR + kb;
                float2 v0 = *(const float2*)(p);
                float2 v1 = *(const float2*)(p + 8 * XSTR);
                float2 v2 = *(const float2*)(p + 8);
                float2 v3 = *(const float2*)(p + 8 * XSTR + 8);
                split2h(v0.x, v0.y, Ah[mt][0], Al[mt][0]);
                split2h(v1.x, v1.y, Ah[mt][1], Al[mt][1]);
                split2h(v2.x, v2.y, Ah[mt][2], Al[mt][2]);
                split2h(v3.x, v3.y, Ah[mt][3], Al[mt][3]);
            }
            #pragma unroll
            for (int nt = 0; nt < 4; nt++) {
                const __half* bp = Bf + (ncol0 + nt * 8 + lr) * KSTR
                                      + kb + lc * 2;
                uint32_t b0 = *(const uint32_t*)bp;
                uint32_t b1 = *(const uint32_t*)(bp + 8);
                #pragma unroll
                for (int mt = 0; mt < 2; mt++) {
                    mma_f16(acc[mt][nt], Ah[mt], b0, b1);
                    mma_f16(acc[mt][nt], Al[mt], b0, b1);
                }
            }
        }

        #pragma unroll
        for (int mt = 0; mt < 2; mt++) {
            int ga = g0 + mrow0 + mt * 16 + lr;
            #pragma unroll
            for (int nt = 0; nt < 4; nt++) {
                int col = ncol0 + nt * 8 + lc * 2;
                float ba = bias[col], bb = bias[col + 1];
                *(float2*)(g_base + (size_t)ga * 128 + col) =
                    make_float2(acc[mt][nt][0] + ba, acc[mt][nt][1] + bb);
                *(float2*)(g_base + (size_t)(ga + 8) * 128 + col) =
                    make_float2(acc[mt][nt][2] + ba, acc[mt][nt][3] + bb);
            }
        }
        return;
    }

    // =================== label body (R12 mainloop, 64 graphs) ==============
    {
        float* Xs  = (float*)smc;                    // [64][LXS]
        float* Hs  = Xs + 64 * LXS;                  // [64][LXS]
        __half* Wf = (__half*)(Hs + 64 * LXS);       // [128][LWS]
        float* w3  = (float*)(Wf + 128 * LWS);       // [128*NL]
        float* b3s = w3 + 128 * NL;                  // [NL]
        float* bias = b3s + 16;                      // [128]

        const int b0 = ((int)blockIdx.x - nBase) * 64;
        const uint32_t xs_u32 = smem_u32(Xs);
        const uint32_t wf_u32 = smem_u32(Wf);

        for (int i = t; i < 128 * NL; i += 256) w3[i] = Wl3[i];
        if (t < NL) b3s[t] = bl3[t];

        const int w = t >> 5, l = t & 31;
        const int lr = l >> 2, lc = l & 3;
        const int mrow0 = (w & 1) * 32;
        const int ncol0 = (w >> 1) * 32;

        float acc[2][4][4];
        #pragma unroll
        for (int mt = 0; mt < 2; mt++)
            #pragma unroll
            for (int nt = 0; nt < 4; nt++)
                #pragma unroll
                for (int j = 0; j < 4; j++) acc[mt][nt][j] = 0.f;

        for (int s = 0; s < 3; s++) {
            __syncthreads();

            #pragma unroll
            for (int i = 0; i < 8; i++) {            // gather X-block
                int f = t + i * 256;
                int g = f >> 5, c4 = (f & 31) << 2;
                int pg = pgi[b0 + g];
                const float* src;
                if (s == 0)      src = node + (size_t)((pg + 1) * n_per - 1) * DD + c4;
                else if (s == 1) src = node + (size_t)pni[b0 + g] * DD + c4;
                else             src = glob + (size_t)pg * DD + c4;
                CP16(xs_u32 + (uint32_t)((g * LXS + c4) * 4), src);
            }
            #pragma unroll
            for (int i = 0; i < 8; i++) {            // W-block: 128 x 256B
                int idx = t + i * 256;
                int row = idx >> 4, c16 = idx & 15;
                CP16(wf_u32 + (uint32_t)(row * (LWS * 2) + c16 * 16),
                     (const float*)(g_wl1 + (size_t)s * 128 * 128
                                    + (size_t)row * 128 + c16 * 8));
            }
            CP_COMMIT();
            CP_WAIT0();
            __syncthreads();

            const float* ab = Xs + (mrow0 + lr) * LXS + lc * 2;
            #pragma unroll
            for (int kc = 0; kc < 8; kc++) {
                const int kb = kc * 16;
                uint32_t Ah[2][4], Al[2][4];
                #pragma unroll
                for (int mt = 0; mt < 2; mt++) {
                    const float* p = ab + mt * 16 * LXS + kb;
                    float2 v0 = *(const float2*)(p);
                    float2 v1 = *(const float2*)(p + 8 * LXS);
                    float2 v2 = *(const float2*)(p + 8);
                    float2 v3 = *(const float2*)(p + 8 * LXS + 8);
                    split2h(v0.x, v0.y, Ah[mt][0], Al[mt][0]);
                    split2h(v1.x, v1.y, Ah[mt][1], Al[mt][1]);
                    split2h(v2.x, v2.y, Ah[mt][2], Al[mt][2]);
                    split2h(v3.x, v3.y, Ah[mt][3], Al[mt][3]);
                }
                #pragma unroll
                for (int nt = 0; nt < 4; nt++) {
                    const __half* bp = Wf + (ncol0 + nt * 8 + lr) * LWS
                                          + kb + lc * 2;
                    uint32_t b0w = *(const uint32_t*)bp;
                    uint32_t b1w = *(const uint32_t*)(bp + 8);
                    #pragma unroll
                    for (int mt = 0; mt < 2; mt++) {
                        mma_f16(acc[mt][nt], Ah[mt], b0w, b1w);
                        mma_f16(acc[mt][nt], Al[mt], b0w, b1w);
                    }
                }
            }
        }

        if (t < 128) bias[t] = bl1[t];
        __syncthreads();

        #pragma unroll
        for (int mt = 0; mt < 2; mt++) {
            int row = mrow0 + mt * 16 + lr;
            #pragma unroll
            for (int nt = 0; nt < 4; nt++) {
                int col = ncol0 + nt * 8 + lc * 2;
                float ba = bias[col], bb = bias[col + 1];
                *(float2*)(Hs + row * LXS + col) = make_float2(
                    fmaxf(acc[mt][nt][0] + ba, 0.f),
                    fmaxf(acc[mt][nt][1] + bb, 0.f));
                *(float2*)(Hs + (row + 8) * LXS + col) = make_float2(
                    fmaxf(acc[mt][nt][2] + ba, 0.f),
                    fmaxf(acc[mt][nt][3] + bb, 0.f));
            }
        }
        __syncthreads();

        #pragma unroll
        for (int i = 0; i < 8; i++) {                // Wl2 via cp.async
            int idx = t + i * 256;
            int row = idx >> 4, c16 = idx & 15;
            CP16(wf_u32 + (uint32_t)(row * (LWS * 2) + c16 * 16),
                 (const float*)(g_wl2 + (size_t)row * 128 + c16 * 8));
        }
        CP_COMMIT();
        if (t < 128) bias[t] = bl2[t];
        CP_WAIT0();
        __syncthreads();

        #pragma unroll
        for (int mt = 0; mt < 2; mt++)
            #pragma unroll
            for (int nt = 0; nt < 4; nt++)
                #pragma unroll
                for (int j = 0; j < 4; j++) acc[mt][nt][j] = 0.f;

        {
            const float* ab = Hs + (mrow0 + lr) * LXS + lc * 2;
            #pragma unroll
            for (int kc = 0; kc < 8; kc++) {
                const int kb = kc * 16;
                uint32_t Ah[2][4], Al[2][4];
                #pragma unroll
                for (int mt = 0; mt < 2; mt++) {
                    const float* p = ab + mt * 16 * LXS + kb;
                    float2 v0 = *(const float2*)(p);
                    float2 v1 = *(const float2*)(p + 8 * LXS);
                    float2 v2 = *(const float2*)(p + 8);
                    float2 v3 = *(const float2*)(p + 8 * LXS + 8);
                    split2h(v0.x, v0.y, Ah[mt][0], Al[mt][0]);
                    split2h(v1.x, v1.y, Ah[mt][1], Al[mt][1]);
                    split2h(v2.x, v2.y, Ah[mt][2], Al[mt][2]);
                    split2h(v3.x, v3.y, Ah[mt][3], Al[mt][3]);
                }
                #pragma unroll
                for (int nt = 0; nt < 4; nt++) {
                    const __half* bp = Wf + (ncol0 + nt * 8 + lr) * LWS
                                          + kb + lc * 2;
                    uint32_t b0w = *(const uint32_t*)bp;
                    uint32_t b1w = *(const uint32_t*)(bp + 8);
                    #pragma unroll
                    for (int mt = 0; mt < 2; mt++) {
                        mma_f16(acc[mt][nt], Ah[mt], b0w, b1w);
                        mma_f16(acc[mt][nt], Al[mt], b0w, b1w);
                    }
                }
            }
        }
        __syncthreads();

        #pragma unroll
        for (int mt = 0; mt < 2; mt++) {
            int row = mrow0 + mt * 16 + lr;
            #pragma unroll
            for (int nt = 0; nt < 4; nt++) {
                int col = ncol0 + nt * 8 + lc * 2;
                float ba = bias[col], bb = bias[col + 1];
                *(float2*)(Xs + row * LXS + col) = make_float2(
                    fmaxf(acc[mt][nt][0] + ba, 0.f),
                    fmaxf(acc[mt][nt][1] + bb, 0.f));
                *(float2*)(Xs + (row + 8) * LXS + col) = make_float2(
                    fmaxf(acc[mt][nt][2] + ba, 0.f),
                    fmaxf(acc[mt][nt][3] + bb, 0.f));
            }
        }
        __syncthreads();

        for (int o = t; o < 64 * NL; o += 256) {
            int g = o / NL, nl = o - g * NL;
            float a = b3s[nl];
            #pragma unroll 4
            for (int k = 0; k < 128; k++)
                a += Xs[g * LXS + k] * w3[k * NL + nl];
            out_label[(size_t)(b0 + g) * NL + nl] = a;
        }
    }
}

// ===========================================================================
// partner kernel (R14-proven mainloop): 256 threads, occ-1, 128-row tiles,
// double-buffered cp.async; Bf staged via cp.async from g_wm scratch.
// ===========================================================================
__global__ void __launch_bounds__(256, 1) partner_kernel(
    const float* __restrict__ node,
    const float* __restrict__ Wp2, const float* __restrict__ bp2,
    float* __restrict__ out, int ntiles)
{
    extern __shared__ char smc[];
    __half* Bf  = (__half*)smc;                      // [128][BSTR]
    float* Ab0  = (float*)(Bf + 128 * BSTR);         // [2][128][ATSTR]
    float* bs0  = Ab0 + 2 * 128 * ATSTR;             // [2][256]
    float* w2s  = bs0 + 512;                         // [128]
    float* srow = w2s + 128;                         // [128][2]

    const int t = threadIdx.x;
    const uint32_t ab_u32 = smem_u32(Ab0);
    const uint32_t bs_u32 = smem_u32(bs0);
    const uint32_t bf_u32 = smem_u32(Bf);

    #pragma unroll
    for (int i = 0; i < 8; i++) {                    // Bf via cp.async
        int idx = t + i * 256;
        int row = idx >> 4, c16 = idx & 15;
        CP16(bf_u32 + (uint32_t)(row * (BSTR * 2) + c16 * 16),
             (const float*)(g_wm + (size_t)row * 128 + c16 * 8));
    }
    if (t < 128) w2s[t] = Wp2[t];
    const float bp2v = bp2[0];

    const int w = t >> 5, l = t & 31;
    const int lr = l >> 2, lc = l & 3;
    const int mrow0 = (w & 3) * 32;
    const int ncol0 = (w >> 2) * 64;
    const int gh = (w & 3) >> 1;

    const int ntloc = (ntiles - (int)blockIdx.x + (int)gridDim.x - 1)
                      / (int)gridDim.x;

    auto issue_tile = [&](int q) {
        int tq = (int)blockIdx.x + q * (int)gridDim.x;
        if (tq < ntiles) {
            const float* src = node + (size_t)tq * (128 * DD);
            const uint32_t du = ab_u32
                + (uint32_t)((q & 1) * 128 * ATSTR * 4);
            #pragma unroll
            for (int i = 0; i < 16; i++) {           // 4096 float4
                int f = t + i * 256;
                int row = f >> 5, c4 = (f & 31) << 2;
                CP16(du + (uint32_t)((row * ATSTR + c4) * 4), src + f * 4);
            }
            if (t < 64) {
                const float* sb = g_base + (size_t)tq * 256 + t * 4;
                CP16(bs_u32 + (uint32_t)(((q & 1) * 256 + t * 4) * 4), sb);
            }
        }
    };

    issue_tile(0); CP_COMMIT();                      // group: {Bf + tile0}
    issue_tile(1); CP_COMMIT();

    for (int q = 0; q < ntloc; q++) {
        const int tq = (int)blockIdx.x + q * (int)gridDim.x;

        CP_WAIT1();
        __syncthreads();

        const float* Abuf  = Ab0 + (q & 1) * (128 * ATSTR);
        const float* base2 = bs0 + (q & 1) * 256;

        float acc[2][8][4];
        #pragma unroll
        for (int mt = 0; mt < 2; mt++)
            #pragma unroll
            for (int nt = 0; nt < 8; nt++)
                #pragma unroll
                for (int j = 0; j < 4; j++) acc[mt][nt][j] = 0.f;

        const float* ab = Abuf + (mrow0 + lr) * ATSTR + lc * 2;

        #pragma unroll
        for (int kc = 0; kc < 8; kc++) {             // sync-free MMA stream
            const int kb = kc * 16;
            uint32_t Ah[2][4];
            #pragma unroll
            for (int mt = 0; mt < 2; mt++) {
                const float* p = ab + mt * 16 * ATSTR + kb;
                float2 v0 = *(const float2*)(p);
                float2 v1 = *(const float2*)(p + 8 * ATSTR);
                float2 v2 = *(const float2*)(p + 8);
                float2 v3 = *(const float2*)(p + 8 * ATSTR + 8);
                Ah[mt][0] = cvt2h(v0.x, v0.y);
                Ah[mt][1] = cvt2h(v1.x, v1.y);
                Ah[mt][2] = cvt2h(v2.x, v2.y);
                Ah[mt][3] = cvt2h(v3.x, v3.y);
            }
            #pragma unroll
            for (int nt = 0; nt < 8; nt++) {
                const __half* bp = Bf + (ncol0 + nt * 8 + lr) * BSTR
                                      + kb + lc * 2;
                uint32_t b0 = *(const uint32_t*)bp;
                uint32_t b1 = *(const uint32_t*)(bp + 8);
                mma_f16(acc[0][nt], Ah[0], b0, b1);
                mma_f16(acc[1][nt], Ah[1], b0, b1);
            }
        }

        // ---- epilogue: relu(acc+base).w2, quad-reduce, combine ----
        float pr[2][2] = {{0.f, 0.f}, {0.f, 0.f}};
        #pragma unroll
        for (int nt = 0; nt < 8; nt++) {
            int c0 = ncol0 + nt * 8 + lc * 2;
            float wa = w2s[c0], wb = w2s[c0 + 1];
            float ba = base2[gh * 128 + c0], bb = base2[gh * 128 + c0 + 1];
            #pragma unroll
            for (int mt = 0; mt < 2; mt++) {
                pr[mt][0] += fmaxf(acc[mt][nt][0] + ba, 0.f) * wa
                           + fmaxf(acc[mt][nt][1] + bb, 0.f) * wb;
                pr[mt][1] += fmaxf(acc[mt][nt][2] + ba, 0.f) * wa
                           + fmaxf(acc[mt][nt][3] + bb, 0.f) * wb;
            }
        }
        #pragma unroll
        for (int o = 1; o <= 2; o <<= 1) {
            pr[0][0] += __shfl_xor_sync(0xffffffffu, pr[0][0], o);
            pr[0][1] += __shfl_xor_sync(0xffffffffu, pr[0][1], o);
            pr[1][0] += __shfl_xor_sync(0xffffffffu, pr[1][0], o);
            pr[1][1] += __shfl_xor_sync(0xffffffffu, pr[1][1], o);
        }
        if (lc == 0) {
            const int cg = w >> 2;
            srow[(mrow0 + lr) * 2 + cg]      = pr[0][0];
            srow[(mrow0 + lr + 8) * 2 + cg]  = pr[0][1];
            srow[(mrow0 + 16 + lr) * 2 + cg] = pr[1][0];
            srow[(mrow0 + 24 + lr) * 2 + cg] = pr[1][1];
        }
        __syncthreads();               // srow ready AND A buffer free
        if (t < 128)
            out[(size_t)tq * 128 + t] = srow[t * 2] + srow[t * 2 + 1] + bp2v;

        issue_tile(q + 2);             // refill the buffer just vacated
        CP_COMMIT();
    }
}

// ===========================================================================
extern "C" void kernel_launch(void* const* d_in, const int* in_sizes, int n_in,
                              void* d_out, int out_size)
{
    const float* node = (const float*)d_in[0];
    const float* glob = (const float*)d_in[1];
    const float* Wp1  = (const float*)d_in[2];
    const float* bp1  = (const float*)d_in[3];
    const float* Wp2  = (const float*)d_in[4];
    const float* bp2  = (const float*)d_in[5];
    const float* Wl1  = (const float*)d_in[6];
    const float* bl1  = (const float*)d_in[7];
    const float* Wl2  = (const float*)d_in[8];
    const float* bl2  = (const float*)d_in[9];
    const float* Wl3  = (const float*)d_in[10];
    const float* bl3  = (const float*)d_in[11];
    const int*   pgi  = (const int*)d_in[12];
    const int*   pni  = (const int*)d_in[13];

    const int N     = in_sizes[0] / DD;
    const int B     = in_sizes[1] / DD;
    const int n_per = N / B;            // 64
    const int NL    = in_sizes[11];     // 14
    const int ntiles = N / 128;         // 4096

    float* out = (float*)d_out;

    const size_t smBase = (size_t)(64 * XSTR) * sizeof(float)
                        + (size_t)(128 * KSTR) * sizeof(__half)
                        + 128 * sizeof(float);
    const size_t smLab  = (size_t)(2 * 64 * LXS) * sizeof(float)
                        + (size_t)(128 * LWS) * sizeof(__half)
                        + (size_t)(128 * NL + 16 + 128) * sizeof(float);
    const size_t smAux  = smBase > smLab ? smBase : smLab;
    const size_t smP = (size_t)(128 * BSTR) * sizeof(__half)
                     + (size_t)(2 * 128 * ATSTR + 512 + 128 + 256)
                       * sizeof(float);

    cudaFuncSetAttribute(aux_kernel,     cudaFuncAttributeMaxDynamicSharedMemorySize, (int)smAux);
    cudaFuncSetAttribute(partner_kernel, cudaFuncAttributeMaxDynamicSharedMemorySize, (int)smP);

    wconv_kernel<<<7, 256>>>(Wp1, Wl1, Wl2);

    const int nBase = B / 64;           // 128 base blocks
    const int nLab  = B / 64;           // 128 label blocks
    aux_kernel<<<nBase + nLab, 256, smAux>>>(node, glob, bp1,
                                             bl1, bl2, Wl3, bl3,
                                             pgi, pni, n_per, NL,
                                             out + (size_t)N, nBase);

    int grid = 148;                     // occ-1 persistent
    if (grid > ntiles) grid = ntiles;
    partner_kernel<<<grid, 256, smP>>>(node, Wp2, bp2, out, ntiles);
}